// round 14
// baseline (speedup 1.0000x reference)
#include <cuda_runtime.h>
#include <cuda_bf16.h>
#include <cstdint>

typedef unsigned int u32;

// Problem constants
#define B_   256
#define S_   512
#define H_   768
#define WDIM 25
#define NLAB 42
#define CIN  2354
#define KPAD 2368   // 74 * 32, zero-padded K
#define MAXW 10

// ctx build split
#define NSEG 4
#define SEGLEN 128

// GEMM1 mma config (128x128 tiles, 256 threads, split-K = 12 via atomics)
#define KS   12
#define NK32 74     // KPAD / 32 k-steps
#define ASTR 40     // A smem row stride (bf16), conflict-free for ldmatrix
#define BSTR 136    // B smem row stride (bf16), conflict-free for ldmatrix

// prep kernel block ranges
#define CTX_BLOCKS   (6 * B_ * NSEG)                    // 6144
#define CONV_BLOCKS  ((CIN * (H_ / 4) + 255) / 256)     // 1766
#define W2T_BLOCKS   ((NLAB * H_) / 256)                // 126
#define HB_BLOCKS    ((B_ * H_) / 256)                  // 768
#define PREP_BLOCKS  (CTX_BLOCKS + CONV_BLOCKS + W2T_BLOCKS + HB_BLOCKS)

// Scratch (no cudaMalloc). Zero-init; pad regions never written -> stay zero.
__device__ __nv_bfloat16 g_Ah[B_ * KPAD];     // comb hi
__device__ __nv_bfloat16 g_Al[B_ * KPAD];     // comb lo
__device__ __nv_bfloat16 g_W1h[KPAD * H_];    // W1 hi
__device__ __nv_bfloat16 g_W1l[KPAD * H_];    // W1 lo
__device__ float g_ctxp[NSEG * B_ * H_];
__device__ float g_hbuf[B_ * H_];             // b1-initialized, atomically accumulated
__device__ float g_W2t[NLAB * H_];            // W2 transposed [42][768]

// ---------------------------------------------------------------------------
// helpers
// ---------------------------------------------------------------------------
__device__ __forceinline__ void split_bf(float x, __nv_bfloat16& h, __nv_bfloat16& l) {
    h = __float2bfloat16(x);
    l = __float2bfloat16(x - __bfloat162float(h));
}
__device__ __forceinline__ unsigned short bfbits(__nv_bfloat16 h) {
    return *reinterpret_cast<unsigned short*>(&h);
}

__device__ __forceinline__ void ldsm_x4(u32& r0, u32& r1, u32& r2, u32& r3, u32 addr) {
    asm volatile("ldmatrix.sync.aligned.m8n8.x4.shared.b16 {%0,%1,%2,%3}, [%4];"
                 : "=r"(r0), "=r"(r1), "=r"(r2), "=r"(r3) : "r"(addr));
}
__device__ __forceinline__ void ldsm_x4t(u32& r0, u32& r1, u32& r2, u32& r3, u32 addr) {
    asm volatile("ldmatrix.sync.aligned.m8n8.x4.trans.shared.b16 {%0,%1,%2,%3}, [%4];"
                 : "=r"(r0), "=r"(r1), "=r"(r2), "=r"(r3) : "r"(addr));
}
__device__ __forceinline__ void mma_bf16(float* d, const u32* a, const u32* b) {
    asm volatile(
        "mma.sync.aligned.m16n8k16.row.col.f32.bf16.bf16.f32 "
        "{%0,%1,%2,%3}, {%4,%5,%6,%7}, {%8,%9}, {%0,%1,%2,%3};"
        : "+f"(d[0]), "+f"(d[1]), "+f"(d[2]), "+f"(d[3])
        : "r"(a[0]), "r"(a[1]), "r"(a[2]), "r"(a[3]), "r"(b[0]), "r"(b[1]));
}

// ---------------------------------------------------------------------------
// Kernel 1 (prep): fused ctx_partial + conv_w1 + w2t + hbuf init
// ---------------------------------------------------------------------------
__global__ __launch_bounds__(256) void prep_kernel(
    const float* __restrict__ seq,
    const int*   __restrict__ e1p,
    const int*   __restrict__ e2p,
    const int*   __restrict__ l1,
    const int*   __restrict__ l2,
    const float* __restrict__ wemb,
    const float* __restrict__ W1,
    const float* __restrict__ W2,
    const float* __restrict__ b1)
{
    const int bid = blockIdx.x;
    const int t   = threadIdx.x;

    if (bid < CTX_BLOCKS) {
        // ---------------- ctx segment partials + entity/width writes ----------------
        const int c   = bid % 6;
        const int b   = (bid / 6) % B_;
        const int seg = bid / (6 * B_);
        const int h0  = c * 128;
        const int w    = t >> 5;
        const int lane = t & 31;

        const int p1 = e1p[b];
        const int p2 = e2p[b];
        const float* base = seq + (size_t)b * S_ * H_;

        if (seg == 0) {
            size_t rb = (size_t)b * KPAD;
            if (t < 128) {
                float x = base[(size_t)p1 * H_ + h0 + t];
                __nv_bfloat16 h, l; split_bf(x, h, l);
                g_Ah[rb + h0 + t] = h; g_Al[rb + h0 + t] = l;
            } else {
                int tt = t - 128;
                float x = base[(size_t)p2 * H_ + h0 + tt];
                __nv_bfloat16 h, l; split_bf(x, h, l);
                g_Ah[rb + H_ + h0 + tt] = h; g_Al[rb + H_ + h0 + tt] = l;
            }
            if (c == 0) {
                if (t < WDIM) {
                    int w1i = min(l1[b], MAXW);
                    float x = wemb[w1i * WDIM + t];
                    __nv_bfloat16 h, l; split_bf(x, h, l);
                    g_Ah[rb + 2 * H_ + t] = h; g_Al[rb + 2 * H_ + t] = l;
                } else if (t >= 32 && t < 32 + WDIM) {
                    int w2i = min(l2[b], MAXW);
                    float x = wemb[w2i * WDIM + (t - 32)];
                    __nv_bfloat16 h, l; split_bf(x, h, l);
                    g_Ah[rb + 2 * H_ + WDIM + (t - 32)] = h;
                    g_Al[rb + 2 * H_ + WDIM + (t - 32)] = l;
                }
            }
        }

        const int lo = max(p1 + 1, seg * SEGLEN);
        const int hi = min(p2, seg * SEGLEN + SEGLEN);

        // predicated 4-deep unroll: positions p, p+8, p+16, p+24 in flight
        float4 a0 = make_float4(0.f, 0.f, 0.f, 0.f);
        float4 a1 = make_float4(0.f, 0.f, 0.f, 0.f);
        float4 a2 = make_float4(0.f, 0.f, 0.f, 0.f);
        float4 a3 = make_float4(0.f, 0.f, 0.f, 0.f);
        for (int p = lo + w; p < hi; p += 32) {
            float4 v0 = __ldcs(((const float4*)(base + (size_t)p * H_ + h0)) + lane);
            a0.x += v0.x; a0.y += v0.y; a0.z += v0.z; a0.w += v0.w;
            if (p + 8 < hi) {
                float4 v1 = __ldcs(((const float4*)(base + (size_t)(p + 8) * H_ + h0)) + lane);
                a1.x += v1.x; a1.y += v1.y; a1.z += v1.z; a1.w += v1.w;
            }
            if (p + 16 < hi) {
                float4 v2 = __ldcs(((const float4*)(base + (size_t)(p + 16) * H_ + h0)) + lane);
                a2.x += v2.x; a2.y += v2.y; a2.z += v2.z; a2.w += v2.w;
            }
            if (p + 24 < hi) {
                float4 v3 = __ldcs(((const float4*)(base + (size_t)(p + 24) * H_ + h0)) + lane);
                a3.x += v3.x; a3.y += v3.y; a3.z += v3.z; a3.w += v3.w;
            }
        }
        a0.x += a1.x + a2.x + a3.x;
        a0.y += a1.y + a2.y + a3.y;
        a0.z += a1.z + a2.z + a3.z;
        a0.w += a1.w + a2.w + a3.w;

        __shared__ float4 red[8][32];
        red[w][lane] = a0;
        __syncthreads();

        if (t < 32) {
            float4 s = red[0][t];
            #pragma unroll
            for (int i = 1; i < 8; i++) {
                float4 v = red[i][t];
                s.x += v.x; s.y += v.y; s.z += v.z; s.w += v.w;
            }
            *(float4*)&g_ctxp[(size_t)seg * (B_ * H_) + (size_t)b * H_ + h0 + t * 4] = s;
        }
    } else if (bid < CTX_BLOCKS + CONV_BLOCKS) {
        // ---------------- W1 fp32 -> bf16 hi/lo ----------------
        int idx = (bid - CTX_BLOCKS) * 256 + t;
        if (idx >= CIN * (H_ / 4)) return;
        int k  = idx / (H_ / 4);
        int n4 = (idx % (H_ / 4)) * 4;
        float4 v = *(const float4*)&W1[(size_t)k * H_ + n4];
        float f[4] = {v.x, v.y, v.z, v.w};
        unsigned short hs4[4], ls4[4];
        #pragma unroll
        for (int i = 0; i < 4; i++) {
            __nv_bfloat16 h, l;
            split_bf(f[i], h, l);
            hs4[i] = bfbits(h); ls4[i] = bfbits(l);
        }
        uint2 ph = make_uint2((u32)hs4[0] | ((u32)hs4[1] << 16), (u32)hs4[2] | ((u32)hs4[3] << 16));
        uint2 pl = make_uint2((u32)ls4[0] | ((u32)ls4[1] << 16), (u32)ls4[2] | ((u32)ls4[3] << 16));
        *(uint2*)&g_W1h[(size_t)k * H_ + n4] = ph;
        *(uint2*)&g_W1l[(size_t)k * H_ + n4] = pl;
    } else if (bid < CTX_BLOCKS + CONV_BLOCKS + W2T_BLOCKS) {
        // ---------------- transpose W2 [768,42] -> [42,768] ----------------
        int idx = (bid - CTX_BLOCKS - CONV_BLOCKS) * 256 + t;
        int n = idx / H_;
        int k = idx % H_;
        g_W2t[idx] = W2[(size_t)k * NLAB + n];
    } else {
        // ---------------- init g_hbuf = b1 (per replay; gemm1 accumulates) ---------
        int idx = (bid - CTX_BLOCKS - CONV_BLOCKS - W2T_BLOCKS) * 256 + t;
        g_hbuf[idx] = b1[idx % H_];
    }
}

// ---------------------------------------------------------------------------
// Kernel 2: combine ctx partials -> bf16 hi/lo cols of comb
//   grid 192 x 256; one 4-col unit per thread, float4 partial loads
// ---------------------------------------------------------------------------
__global__ __launch_bounds__(256) void ctx_combine_kernel(
    const int* __restrict__ e1p,
    const int* __restrict__ e2p)
{
    int idx = blockIdx.x * 256 + threadIdx.x;   // B_*H_/4 = 49152 exact
    int b  = idx / (H_ / 4);
    int j4 = (idx % (H_ / 4)) * 4;

    const int cnt = e2p[b] - e1p[b] - 1;
    const float inv = (cnt > 0) ? (1.0f / (float)cnt) : 0.0f;

    float4 s = *(const float4*)&g_ctxp[(size_t)b * H_ + j4];
    #pragma unroll
    for (int seg = 1; seg < NSEG; seg++) {
        float4 v = *(const float4*)&g_ctxp[(size_t)seg * (B_ * H_) + (size_t)b * H_ + j4];
        s.x += v.x; s.y += v.y; s.z += v.z; s.w += v.w;
    }
    float f[4] = {s.x * inv, s.y * inv, s.z * inv, s.w * inv};
    unsigned short hs4[4], ls4[4];
    #pragma unroll
    for (int i = 0; i < 4; i++) {
        __nv_bfloat16 h, l;
        split_bf(f[i], h, l);
        hs4[i] = bfbits(h); ls4[i] = bfbits(l);
    }
    // element offset = b*KPAD + 1586 + j4  (even -> 4B-aligned u32 stores)
    size_t o = (size_t)b * KPAD + 2 * H_ + 2 * WDIM + j4;
    *(u32*)&g_Ah[o]     = (u32)hs4[0] | ((u32)hs4[1] << 16);
    *(u32*)&g_Ah[o + 2] = (u32)hs4[2] | ((u32)hs4[3] << 16);
    *(u32*)&g_Al[o]     = (u32)ls4[0] | ((u32)ls4[1] << 16);
    *(u32*)&g_Al[o + 2] = (u32)ls4[2] | ((u32)ls4[3] << 16);
}

// ---------------------------------------------------------------------------
// Kernel 3: GEMM1 via mma.sync bf16 hi/lo split.
//   grid (6, 2, 12) = 144 CTAs; block 256 = 8 warps 4(m) x 2(n); warp 32x64
//   Epilogue: atomicAdd into g_hbuf (no partial buffer)
// ---------------------------------------------------------------------------
__global__ __launch_bounds__(256, 1) void gemm1_mma_kernel()
{
    __shared__ __nv_bfloat16 sAh[128 * ASTR];
    __shared__ __nv_bfloat16 sAl[128 * ASTR];
    __shared__ __nv_bfloat16 sBh[32 * BSTR];
    __shared__ __nv_bfloat16 sBl[32 * BSTR];

    const int tid = threadIdx.x;
    const int wid = tid >> 5, lane = tid & 31;
    const int bn = blockIdx.x, bm = blockIdx.y, ks = blockIdx.z;
    const int row0 = bm * 128, col0 = bn * 128;
    const int t0 = (NK32 * ks) / KS, t1 = (NK32 * (ks + 1)) / KS;

    const int wm = wid >> 1, wn = wid & 1;
    const int m0 = wm * 32, n0 = wn * 64;

    const int arow = tid >> 1, ahalf = tid & 1;
    const int brow = tid >> 3, bq = tid & 7;

    float acc[2][8][4] = {};
    uint4 pAh[2], pAl[2], pBh[2], pBl[2];

    {
        int kt = t0 * 32;
        const __nv_bfloat16* gA   = &g_Ah[(size_t)(row0 + arow) * KPAD + kt + ahalf * 16];
        const __nv_bfloat16* gAl_ = &g_Al[(size_t)(row0 + arow) * KPAD + kt + ahalf * 16];
        pAh[0] = *(const uint4*)(gA);      pAh[1] = *(const uint4*)(gA + 8);
        pAl[0] = *(const uint4*)(gAl_);    pAl[1] = *(const uint4*)(gAl_ + 8);
        const __nv_bfloat16* gB   = &g_W1h[(size_t)(kt + brow) * H_ + col0];
        const __nv_bfloat16* gBl_ = &g_W1l[(size_t)(kt + brow) * H_ + col0];
        pBh[0] = *(const uint4*)(gB + bq * 8);     pBh[1] = *(const uint4*)(gB + (bq + 8) * 8);
        pBl[0] = *(const uint4*)(gBl_ + bq * 8);   pBl[1] = *(const uint4*)(gBl_ + (bq + 8) * 8);
    }

    for (int t = t0; t < t1; t++) {
        *(uint4*)&sAh[arow * ASTR + ahalf * 16]     = pAh[0];
        *(uint4*)&sAh[arow * ASTR + ahalf * 16 + 8] = pAh[1];
        *(uint4*)&sAl[arow * ASTR + ahalf * 16]     = pAl[0];
        *(uint4*)&sAl[arow * ASTR + ahalf * 16 + 8] = pAl[1];
        *(uint4*)&sBh[brow * BSTR + bq * 8]         = pBh[0];
        *(uint4*)&sBh[brow * BSTR + (bq + 8) * 8]   = pBh[1];
        *(uint4*)&sBl[brow * BSTR + bq * 8]         = pBl[0];
        *(uint4*)&sBl[brow * BSTR + (bq + 8) * 8]   = pBl[1];
        __syncthreads();

        if (t + 1 < t1) {
            int kt = (t + 1) * 32;
            const __nv_bfloat16* gA   = &g_Ah[(size_t)(row0 + arow) * KPAD + kt + ahalf * 16];
            const __nv_bfloat16* gAl_ = &g_Al[(size_t)(row0 + arow) * KPAD + kt + ahalf * 16];
            pAh[0] = *(const uint4*)(gA);      pAh[1] = *(const uint4*)(gA + 8);
            pAl[0] = *(const uint4*)(gAl_);    pAl[1] = *(const uint4*)(gAl_ + 8);
            const __nv_bfloat16* gB   = &g_W1h[(size_t)(kt + brow) * H_ + col0];
            const __nv_bfloat16* gBl_ = &g_W1l[(size_t)(kt + brow) * H_ + col0];
            pBh[0] = *(const uint4*)(gB + bq * 8);     pBh[1] = *(const uint4*)(gB + (bq + 8) * 8);
            pBl[0] = *(const uint4*)(gBl_ + bq * 8);   pBl[1] = *(const uint4*)(gBl_ + (bq + 8) * 8);
        }

        #pragma unroll
        for (int kk = 0; kk < 32; kk += 16) {
            u32 aH[2][4], aL[2][4], bH[8][2], bL[8][2];
            #pragma unroll
            for (int mi = 0; mi < 2; mi++) {
                u32 off = (u32)((m0 + mi * 16 + (lane & 15)) * ASTR + kk + ((lane >> 4) << 3)) * 2;
                ldsm_x4(aH[mi][0], aH[mi][1], aH[mi][2], aH[mi][3],
                        (u32)__cvta_generic_to_shared(sAh) + off);
                ldsm_x4(aL[mi][0], aL[mi][1], aL[mi][2], aL[mi][3],
                        (u32)__cvta_generic_to_shared(sAl) + off);
            }
            #pragma unroll
            for (int nj = 0; nj < 4; nj++) {
                u32 off = (u32)((kk + (lane & 15)) * BSTR + n0 + nj * 16 + ((lane >> 4) << 3)) * 2;
                ldsm_x4t(bH[nj * 2][0], bH[nj * 2][1], bH[nj * 2 + 1][0], bH[nj * 2 + 1][1],
                         (u32)__cvta_generic_to_shared(sBh) + off);
                ldsm_x4t(bL[nj * 2][0], bL[nj * 2][1], bL[nj * 2 + 1][0], bL[nj * 2 + 1][1],
                         (u32)__cvta_generic_to_shared(sBl) + off);
            }
            #pragma unroll
            for (int mi = 0; mi < 2; mi++)
                #pragma unroll
                for (int nf = 0; nf < 8; nf++) {
                    mma_bf16(acc[mi][nf], aH[mi], bH[nf]);
                    mma_bf16(acc[mi][nf], aH[mi], bL[nf]);
                    mma_bf16(acc[mi][nf], aL[mi], bH[nf]);
                }
        }
        __syncthreads();
    }

    // epilogue: atomic accumulate into g_hbuf (spread addresses -> REDG)
    #pragma unroll
    for (int mi = 0; mi < 2; mi++) {
        int r = row0 + m0 + mi * 16 + (lane >> 2);
        #pragma unroll
        for (int nf = 0; nf < 8; nf++) {
            int cc = col0 + n0 + nf * 8 + (lane & 3) * 2;
            atomicAdd(&g_hbuf[(size_t)r * H_ + cc],           acc[mi][nf][0]);
            atomicAdd(&g_hbuf[(size_t)r * H_ + cc + 1],       acc[mi][nf][1]);
            atomicAdd(&g_hbuf[(size_t)(r + 8) * H_ + cc],     acc[mi][nf][2]);
            atomicAdd(&g_hbuf[(size_t)(r + 8) * H_ + cc + 1], acc[mi][nf][3]);
        }
    }
}

// ---------------------------------------------------------------------------
// Kernel 4: relu + GEMM2 -> logits   (grid B x 256, 8 warps)
// ---------------------------------------------------------------------------
__global__ __launch_bounds__(256) void gemm2_kernel(
    const float* __restrict__ b2,
    float*       __restrict__ out)
{
    __shared__ float hs[H_];
    const int b = blockIdx.x;
    const int t = threadIdx.x;

    #pragma unroll
    for (int j = t; j < H_; j += 256)
        hs[j] = fmaxf(g_hbuf[(size_t)b * H_ + j], 0.0f);
    __syncthreads();

    const int w = t >> 5, lane = t & 31;
    for (int n = w; n < NLAB; n += 8) {
        float s = 0.0f;
        #pragma unroll
        for (int i = 0; i < 6; i++) {
            int k4 = lane + 32 * i;
            float4 hv = *(const float4*)&hs[k4 * 4];
            float4 wv = *(const float4*)&g_W2t[(size_t)n * H_ + k4 * 4];
            s += hv.x * wv.x + hv.y * wv.y + hv.z * wv.z + hv.w * wv.w;
        }
        #pragma unroll
        for (int off = 16; off > 0; off >>= 1)
            s += __shfl_down_sync(0xFFFFFFFFu, s, off);
        if (lane == 0) out[(size_t)b * NLAB + n] = s + b2[n];
    }
}

// ---------------------------------------------------------------------------
extern "C" void kernel_launch(void* const* d_in, const int* in_sizes, int n_in,
                              void* d_out, int out_size)
{
    const float* seq   = (const float*)d_in[0];
    const int*   e1p   = (const int*)  d_in[1];
    const int*   e2p   = (const int*)  d_in[2];
    const int*   l1    = (const int*)  d_in[3];
    const int*   l2    = (const int*)  d_in[4];
    const float* wemb  = (const float*)d_in[5];
    const float* W1    = (const float*)d_in[6];
    const float* b1    = (const float*)d_in[7];
    const float* W2    = (const float*)d_in[8];
    const float* b2    = (const float*)d_in[9];
    float* out = (float*)d_out;

    prep_kernel<<<PREP_BLOCKS, 256>>>(seq, e1p, e2p, l1, l2, wemb, W1, W2, b1);
    ctx_combine_kernel<<<(B_ * H_ / 4) / 256, 256>>>(e1p, e2p);
    gemm1_mma_kernel<<<dim3(6, 2, KS), 256>>>();
    gemm2_kernel<<<B_, 256>>>(b2, out);
}

// round 15
// speedup vs baseline: 1.0477x; 1.0477x over previous
#include <cuda_runtime.h>
#include <cuda_bf16.h>
#include <cstdint>

typedef unsigned int u32;

// Problem constants
#define B_   256
#define S_   512
#define H_   768
#define WDIM 25
#define NLAB 42
#define CIN  2354
#define KPAD 2368   // 74 * 32, zero-padded K
#define MAXW 10

// ctx build split
#define NSEG 4

// GEMM1 mma config (128x128 tiles, 256 threads, split-K = 12 via atomics)
#define KS   12
#define NK32 74     // KPAD / 32 k-steps
#define ASTR 40     // A smem row stride (bf16), conflict-free for ldmatrix
#define BSTR 136    // B smem row stride (bf16), conflict-free for ldmatrix

// prep kernel block ranges
#define CTX_BLOCKS   (6 * B_ * NSEG)                    // 6144
#define CONV_BLOCKS  ((CIN * (H_ / 4) + 255) / 256)     // 1766
#define W2T_BLOCKS   ((NLAB * H_) / 256)                // 126
#define HB_BLOCKS    ((B_ * H_) / 256)                  // 768
#define PREP_BLOCKS  (CTX_BLOCKS + CONV_BLOCKS + W2T_BLOCKS + HB_BLOCKS)

// Scratch (no cudaMalloc). Zero-init; pad regions never written -> stay zero.
__device__ __nv_bfloat16 g_Ah[B_ * KPAD];     // comb hi
__device__ __nv_bfloat16 g_Al[B_ * KPAD];     // comb lo
__device__ __nv_bfloat16 g_W1h[KPAD * H_];    // W1 hi
__device__ __nv_bfloat16 g_W1l[KPAD * H_];    // W1 lo
__device__ float g_ctxp[NSEG * B_ * H_];
__device__ float g_hbuf[B_ * H_];             // b1-initialized, atomically accumulated
__device__ float g_W2t[NLAB * H_];            // W2 transposed [42][768]

// ---------------------------------------------------------------------------
// helpers
// ---------------------------------------------------------------------------
__device__ __forceinline__ void split_bf(float x, __nv_bfloat16& h, __nv_bfloat16& l) {
    h = __float2bfloat16(x);
    l = __float2bfloat16(x - __bfloat162float(h));
}
__device__ __forceinline__ unsigned short bfbits(__nv_bfloat16 h) {
    return *reinterpret_cast<unsigned short*>(&h);
}

__device__ __forceinline__ void ldsm_x4(u32& r0, u32& r1, u32& r2, u32& r3, u32 addr) {
    asm volatile("ldmatrix.sync.aligned.m8n8.x4.shared.b16 {%0,%1,%2,%3}, [%4];"
                 : "=r"(r0), "=r"(r1), "=r"(r2), "=r"(r3) : "r"(addr));
}
__device__ __forceinline__ void ldsm_x4t(u32& r0, u32& r1, u32& r2, u32& r3, u32 addr) {
    asm volatile("ldmatrix.sync.aligned.m8n8.x4.trans.shared.b16 {%0,%1,%2,%3}, [%4];"
                 : "=r"(r0), "=r"(r1), "=r"(r2), "=r"(r3) : "r"(addr));
}
__device__ __forceinline__ void mma_bf16(float* d, const u32* a, const u32* b) {
    asm volatile(
        "mma.sync.aligned.m16n8k16.row.col.f32.bf16.bf16.f32 "
        "{%0,%1,%2,%3}, {%4,%5,%6,%7}, {%8,%9}, {%0,%1,%2,%3};"
        : "+f"(d[0]), "+f"(d[1]), "+f"(d[2]), "+f"(d[3])
        : "r"(a[0]), "r"(a[1]), "r"(a[2]), "r"(a[3]), "r"(b[0]), "r"(b[1]));
}

// ---------------------------------------------------------------------------
// Kernel 1 (prep): fused ctx_partial + conv_w1 + w2t + hbuf init
// ---------------------------------------------------------------------------
__global__ __launch_bounds__(256) void prep_kernel(
    const float* __restrict__ seq,
    const int*   __restrict__ e1p,
    const int*   __restrict__ e2p,
    const int*   __restrict__ l1,
    const int*   __restrict__ l2,
    const float* __restrict__ wemb,
    const float* __restrict__ W1,
    const float* __restrict__ W2,
    const float* __restrict__ b1)
{
    const int bid = blockIdx.x;
    const int t   = threadIdx.x;

    if (bid < CTX_BLOCKS) {
        // ---------------- ctx segment partials + entity/width writes ----------------
        const int c   = bid % 6;
        const int b   = (bid / 6) % B_;
        const int seg = bid / (6 * B_);
        const int h0  = c * 128;
        const int w    = t >> 5;
        const int lane = t & 31;

        const int p1 = e1p[b];
        const int p2 = e2p[b];
        const float* base = seq + (size_t)b * S_ * H_;

        if (seg == 0) {
            size_t rb = (size_t)b * KPAD;
            if (t < 128) {
                float x = base[(size_t)p1 * H_ + h0 + t];
                __nv_bfloat16 h, l; split_bf(x, h, l);
                g_Ah[rb + h0 + t] = h; g_Al[rb + h0 + t] = l;
            } else {
                int tt = t - 128;
                float x = base[(size_t)p2 * H_ + h0 + tt];
                __nv_bfloat16 h, l; split_bf(x, h, l);
                g_Ah[rb + H_ + h0 + tt] = h; g_Al[rb + H_ + h0 + tt] = l;
            }
            if (c == 0) {
                if (t < WDIM) {
                    int w1i = min(l1[b], MAXW);
                    float x = wemb[w1i * WDIM + t];
                    __nv_bfloat16 h, l; split_bf(x, h, l);
                    g_Ah[rb + 2 * H_ + t] = h; g_Al[rb + 2 * H_ + t] = l;
                } else if (t >= 32 && t < 32 + WDIM) {
                    int w2i = min(l2[b], MAXW);
                    float x = wemb[w2i * WDIM + (t - 32)];
                    __nv_bfloat16 h, l; split_bf(x, h, l);
                    g_Ah[rb + 2 * H_ + WDIM + (t - 32)] = h;
                    g_Al[rb + 2 * H_ + WDIM + (t - 32)] = l;
                }
            }
        }

        // dynamic span quartering: equal work per segment block
        const int sstart = p1 + 1;
        const int len    = max(p2 - sstart, 0);
        const int lo     = sstart + (len * seg) / NSEG;
        const int hi     = sstart + (len * (seg + 1)) / NSEG;   // exclusive

        float4 acc0 = make_float4(0.f, 0.f, 0.f, 0.f);
        float4 acc1 = make_float4(0.f, 0.f, 0.f, 0.f);
        int p = lo + w;
        for (; p + 8 < hi; p += 16) {
            float4 v0 = __ldcs(((const float4*)(base + (size_t)p * H_ + h0)) + lane);
            float4 v1 = __ldcs(((const float4*)(base + (size_t)(p + 8) * H_ + h0)) + lane);
            acc0.x += v0.x; acc0.y += v0.y; acc0.z += v0.z; acc0.w += v0.w;
            acc1.x += v1.x; acc1.y += v1.y; acc1.z += v1.z; acc1.w += v1.w;
        }
        if (p < hi) {
            float4 v0 = __ldcs(((const float4*)(base + (size_t)p * H_ + h0)) + lane);
            acc0.x += v0.x; acc0.y += v0.y; acc0.z += v0.z; acc0.w += v0.w;
        }
        acc0.x += acc1.x; acc0.y += acc1.y; acc0.z += acc1.z; acc0.w += acc1.w;

        __shared__ float4 red[8][32];
        red[w][lane] = acc0;
        __syncthreads();

        if (t < 32) {
            float4 s = red[0][t];
            #pragma unroll
            for (int i = 1; i < 8; i++) {
                float4 v = red[i][t];
                s.x += v.x; s.y += v.y; s.z += v.z; s.w += v.w;
            }
            *(float4*)&g_ctxp[(size_t)seg * (B_ * H_) + (size_t)b * H_ + h0 + t * 4] = s;
        }
    } else if (bid < CTX_BLOCKS + CONV_BLOCKS) {
        // ---------------- W1 fp32 -> bf16 hi/lo ----------------
        int idx = (bid - CTX_BLOCKS) * 256 + t;
        if (idx >= CIN * (H_ / 4)) return;
        int k  = idx / (H_ / 4);
        int n4 = (idx % (H_ / 4)) * 4;
        float4 v = *(const float4*)&W1[(size_t)k * H_ + n4];
        float f[4] = {v.x, v.y, v.z, v.w};
        unsigned short hs4[4], ls4[4];
        #pragma unroll
        for (int i = 0; i < 4; i++) {
            __nv_bfloat16 h, l;
            split_bf(f[i], h, l);
            hs4[i] = bfbits(h); ls4[i] = bfbits(l);
        }
        uint2 ph = make_uint2((u32)hs4[0] | ((u32)hs4[1] << 16), (u32)hs4[2] | ((u32)hs4[3] << 16));
        uint2 pl = make_uint2((u32)ls4[0] | ((u32)ls4[1] << 16), (u32)ls4[2] | ((u32)ls4[3] << 16));
        *(uint2*)&g_W1h[(size_t)k * H_ + n4] = ph;
        *(uint2*)&g_W1l[(size_t)k * H_ + n4] = pl;
    } else if (bid < CTX_BLOCKS + CONV_BLOCKS + W2T_BLOCKS) {
        // ---------------- transpose W2 [768,42] -> [42,768] ----------------
        int idx = (bid - CTX_BLOCKS - CONV_BLOCKS) * 256 + t;
        int n = idx / H_;
        int k = idx % H_;
        g_W2t[idx] = W2[(size_t)k * NLAB + n];
    } else {
        // ---------------- init g_hbuf = b1 (per replay; gemm1 accumulates) ---------
        int idx = (bid - CTX_BLOCKS - CONV_BLOCKS - W2T_BLOCKS) * 256 + t;
        g_hbuf[idx] = b1[idx % H_];
    }
}

// ---------------------------------------------------------------------------
// Kernel 2: combine ctx partials -> bf16 hi/lo cols of comb
//   grid 192 x 256; one 4-col unit per thread, float4 partial loads
// ---------------------------------------------------------------------------
__global__ __launch_bounds__(256) void ctx_combine_kernel(
    const int* __restrict__ e1p,
    const int* __restrict__ e2p)
{
    int idx = blockIdx.x * 256 + threadIdx.x;   // B_*H_/4 = 49152 exact
    int b  = idx / (H_ / 4);
    int j4 = (idx % (H_ / 4)) * 4;

    const int cnt = e2p[b] - e1p[b] - 1;
    const float inv = (cnt > 0) ? (1.0f / (float)cnt) : 0.0f;

    float4 s = *(const float4*)&g_ctxp[(size_t)b * H_ + j4];
    #pragma unroll
    for (int seg = 1; seg < NSEG; seg++) {
        float4 v = *(const float4*)&g_ctxp[(size_t)seg * (B_ * H_) + (size_t)b * H_ + j4];
        s.x += v.x; s.y += v.y; s.z += v.z; s.w += v.w;
    }
    float f[4] = {s.x * inv, s.y * inv, s.z * inv, s.w * inv};
    unsigned short hs4[4], ls4[4];
    #pragma unroll
    for (int i = 0; i < 4; i++) {
        __nv_bfloat16 h, l;
        split_bf(f[i], h, l);
        hs4[i] = bfbits(h); ls4[i] = bfbits(l);
    }
    // element offset = b*KPAD + 1586 + j4  (even -> 4B-aligned u32 stores)
    size_t o = (size_t)b * KPAD + 2 * H_ + 2 * WDIM + j4;
    *(u32*)&g_Ah[o]     = (u32)hs4[0] | ((u32)hs4[1] << 16);
    *(u32*)&g_Ah[o + 2] = (u32)hs4[2] | ((u32)hs4[3] << 16);
    *(u32*)&g_Al[o]     = (u32)ls4[0] | ((u32)ls4[1] << 16);
    *(u32*)&g_Al[o + 2] = (u32)ls4[2] | ((u32)ls4[3] << 16);
}

// ---------------------------------------------------------------------------
// Kernel 3: GEMM1 via mma.sync bf16 hi/lo split.
//   grid (6, 2, 12) = 144 CTAs; block 256 = 8 warps 4(m) x 2(n); warp 32x64
//   Epilogue: atomicAdd into g_hbuf (no partial buffer)
// ---------------------------------------------------------------------------
__global__ __launch_bounds__(256, 1) void gemm1_mma_kernel()
{
    __shared__ __nv_bfloat16 sAh[128 * ASTR];
    __shared__ __nv_bfloat16 sAl[128 * ASTR];
    __shared__ __nv_bfloat16 sBh[32 * BSTR];
    __shared__ __nv_bfloat16 sBl[32 * BSTR];

    const int tid = threadIdx.x;
    const int wid = tid >> 5, lane = tid & 31;
    const int bn = blockIdx.x, bm = blockIdx.y, ks = blockIdx.z;
    const int row0 = bm * 128, col0 = bn * 128;
    const int t0 = (NK32 * ks) / KS, t1 = (NK32 * (ks + 1)) / KS;

    const int wm = wid >> 1, wn = wid & 1;
    const int m0 = wm * 32, n0 = wn * 64;

    const int arow = tid >> 1, ahalf = tid & 1;
    const int brow = tid >> 3, bq = tid & 7;

    float acc[2][8][4] = {};
    uint4 pAh[2], pAl[2], pBh[2], pBl[2];

    {
        int kt = t0 * 32;
        const __nv_bfloat16* gA   = &g_Ah[(size_t)(row0 + arow) * KPAD + kt + ahalf * 16];
        const __nv_bfloat16* gAl_ = &g_Al[(size_t)(row0 + arow) * KPAD + kt + ahalf * 16];
        pAh[0] = *(const uint4*)(gA);      pAh[1] = *(const uint4*)(gA + 8);
        pAl[0] = *(const uint4*)(gAl_);    pAl[1] = *(const uint4*)(gAl_ + 8);
        const __nv_bfloat16* gB   = &g_W1h[(size_t)(kt + brow) * H_ + col0];
        const __nv_bfloat16* gBl_ = &g_W1l[(size_t)(kt + brow) * H_ + col0];
        pBh[0] = *(const uint4*)(gB + bq * 8);     pBh[1] = *(const uint4*)(gB + (bq + 8) * 8);
        pBl[0] = *(const uint4*)(gBl_ + bq * 8);   pBl[1] = *(const uint4*)(gBl_ + (bq + 8) * 8);
    }

    for (int t = t0; t < t1; t++) {
        *(uint4*)&sAh[arow * ASTR + ahalf * 16]     = pAh[0];
        *(uint4*)&sAh[arow * ASTR + ahalf * 16 + 8] = pAh[1];
        *(uint4*)&sAl[arow * ASTR + ahalf * 16]     = pAl[0];
        *(uint4*)&sAl[arow * ASTR + ahalf * 16 + 8] = pAl[1];
        *(uint4*)&sBh[brow * BSTR + bq * 8]         = pBh[0];
        *(uint4*)&sBh[brow * BSTR + (bq + 8) * 8]   = pBh[1];
        *(uint4*)&sBl[brow * BSTR + bq * 8]         = pBl[0];
        *(uint4*)&sBl[brow * BSTR + (bq + 8) * 8]   = pBl[1];
        __syncthreads();

        if (t + 1 < t1) {
            int kt = (t + 1) * 32;
            const __nv_bfloat16* gA   = &g_Ah[(size_t)(row0 + arow) * KPAD + kt + ahalf * 16];
            const __nv_bfloat16* gAl_ = &g_Al[(size_t)(row0 + arow) * KPAD + kt + ahalf * 16];
            pAh[0] = *(const uint4*)(gA);      pAh[1] = *(const uint4*)(gA + 8);
            pAl[0] = *(const uint4*)(gAl_);    pAl[1] = *(const uint4*)(gAl_ + 8);
            const __nv_bfloat16* gB   = &g_W1h[(size_t)(kt + brow) * H_ + col0];
            const __nv_bfloat16* gBl_ = &g_W1l[(size_t)(kt + brow) * H_ + col0];
            pBh[0] = *(const uint4*)(gB + bq * 8);     pBh[1] = *(const uint4*)(gB + (bq + 8) * 8);
            pBl[0] = *(const uint4*)(gBl_ + bq * 8);   pBl[1] = *(const uint4*)(gBl_ + (bq + 8) * 8);
        }

        #pragma unroll
        for (int kk = 0; kk < 32; kk += 16) {
            u32 aH[2][4], aL[2][4], bH[8][2], bL[8][2];
            #pragma unroll
            for (int mi = 0; mi < 2; mi++) {
                u32 off = (u32)((m0 + mi * 16 + (lane & 15)) * ASTR + kk + ((lane >> 4) << 3)) * 2;
                ldsm_x4(aH[mi][0], aH[mi][1], aH[mi][2], aH[mi][3],
                        (u32)__cvta_generic_to_shared(sAh) + off);
                ldsm_x4(aL[mi][0], aL[mi][1], aL[mi][2], aL[mi][3],
                        (u32)__cvta_generic_to_shared(sAl) + off);
            }
            #pragma unroll
            for (int nj = 0; nj < 4; nj++) {
                u32 off = (u32)((kk + (lane & 15)) * BSTR + n0 + nj * 16 + ((lane >> 4) << 3)) * 2;
                ldsm_x4t(bH[nj * 2][0], bH[nj * 2][1], bH[nj * 2 + 1][0], bH[nj * 2 + 1][1],
                         (u32)__cvta_generic_to_shared(sBh) + off);
                ldsm_x4t(bL[nj * 2][0], bL[nj * 2][1], bL[nj * 2 + 1][0], bL[nj * 2 + 1][1],
                         (u32)__cvta_generic_to_shared(sBl) + off);
            }
            #pragma unroll
            for (int mi = 0; mi < 2; mi++)
                #pragma unroll
                for (int nf = 0; nf < 8; nf++) {
                    mma_bf16(acc[mi][nf], aH[mi], bH[nf]);
                    mma_bf16(acc[mi][nf], aH[mi], bL[nf]);
                    mma_bf16(acc[mi][nf], aL[mi], bH[nf]);
                }
        }
        __syncthreads();
    }

    // epilogue: atomic accumulate into g_hbuf (spread addresses -> REDG)
    #pragma unroll
    for (int mi = 0; mi < 2; mi++) {
        int r = row0 + m0 + mi * 16 + (lane >> 2);
        #pragma unroll
        for (int nf = 0; nf < 8; nf++) {
            int cc = col0 + n0 + nf * 8 + (lane & 3) * 2;
            atomicAdd(&g_hbuf[(size_t)r * H_ + cc],           acc[mi][nf][0]);
            atomicAdd(&g_hbuf[(size_t)r * H_ + cc + 1],       acc[mi][nf][1]);
            atomicAdd(&g_hbuf[(size_t)(r + 8) * H_ + cc],     acc[mi][nf][2]);
            atomicAdd(&g_hbuf[(size_t)(r + 8) * H_ + cc + 1], acc[mi][nf][3]);
        }
    }
}

// ---------------------------------------------------------------------------
// Kernel 4: relu + GEMM2 -> logits   (grid B x 256, 8 warps)
// ---------------------------------------------------------------------------
__global__ __launch_bounds__(256) void gemm2_kernel(
    const float* __restrict__ b2,
    float*       __restrict__ out)
{
    __shared__ float hs[H_];
    const int b = blockIdx.x;
    const int t = threadIdx.x;

    #pragma unroll
    for (int j = t; j < H_; j += 256)
        hs[j] = fmaxf(g_hbuf[(size_t)b * H_ + j], 0.0f);
    __syncthreads();

    const int w = t >> 5, lane = t & 31;
    for (int n = w; n < NLAB; n += 8) {
        float s = 0.0f;
        #pragma unroll
        for (int i = 0; i < 6; i++) {
            int k4 = lane + 32 * i;
            float4 hv = *(const float4*)&hs[k4 * 4];
            float4 wv = *(const float4*)&g_W2t[(size_t)n * H_ + k4 * 4];
            s += hv.x * wv.x + hv.y * wv.y + hv.z * wv.z + hv.w * wv.w;
        }
        #pragma unroll
        for (int off = 16; off > 0; off >>= 1)
            s += __shfl_down_sync(0xFFFFFFFFu, s, off);
        if (lane == 0) out[(size_t)b * NLAB + n] = s + b2[n];
    }
}

// ---------------------------------------------------------------------------
extern "C" void kernel_launch(void* const* d_in, const int* in_sizes, int n_in,
                              void* d_out, int out_size)
{
    const float* seq   = (const float*)d_in[0];
    const int*   e1p   = (const int*)  d_in[1];
    const int*   e2p   = (const int*)  d_in[2];
    const int*   l1    = (const int*)  d_in[3];
    const int*   l2    = (const int*)  d_in[4];
    const float* wemb  = (const float*)d_in[5];
    const float* W1    = (const float*)d_in[6];
    const float* b1    = (const float*)d_in[7];
    const float* W2    = (const float*)d_in[8];
    const float* b2    = (const float*)d_in[9];
    float* out = (float*)d_out;

    prep_kernel<<<PREP_BLOCKS, 256>>>(seq, e1p, e2p, l1, l2, wemb, W1, W2, b1);
    ctx_combine_kernel<<<(B_ * H_ / 4) / 256, 256>>>(e1p, e2p);
    gemm1_mma_kernel<<<dim3(6, 2, KS), 256>>>();
    gemm2_kernel<<<B_, 256>>>(b2, out);
}